// round 2
// baseline (speedup 1.0000x reference)
#include <cuda_runtime.h>

#define SGRID 14
#define BATCH 4096
#define NCELLS (BATCH * SGRID * SGRID)   // 802816
#define THREADS 128
#define CPB 128                          // cells per block
#define F4_PER_TILE (CPB * 30 / 4)       // 960 float4 per tensor per block

__global__ void init_out_kernel(float* out) {
    if (threadIdx.x == 0 && blockIdx.x == 0) out[0] = 0.0f;
}

__global__ void __launch_bounds__(THREADS)
yolo_loss_kernel(const float* __restrict__ pred,
                 const float* __restrict__ targ,
                 float* __restrict__ out)
{
    __shared__ float sp[CPB * 30];
    __shared__ float st[CPB * 30];

    const size_t base = (size_t)blockIdx.x * (CPB * 30);
    const float4* gp = reinterpret_cast<const float4*>(pred + base);
    const float4* gt = reinterpret_cast<const float4*>(targ + base);
    float4* s4p = reinterpret_cast<float4*>(sp);
    float4* s4t = reinterpret_cast<float4*>(st);

    // ---- coalesced stage: registers first (MLP=8), then STS ----
    {
        float4 rp[8];
#pragma unroll
        for (int j = 0; j < 8; j++) {
            int i = threadIdx.x + j * THREADS;
            if (i < F4_PER_TILE) rp[j] = __ldg(gp + i);
        }
#pragma unroll
        for (int j = 0; j < 8; j++) {
            int i = threadIdx.x + j * THREADS;
            if (i < F4_PER_TILE) s4p[i] = rp[j];
        }
        float4 rt[8];
#pragma unroll
        for (int j = 0; j < 8; j++) {
            int i = threadIdx.x + j * THREADS;
            if (i < F4_PER_TILE) rt[j] = __ldg(gt + i);
        }
#pragma unroll
        for (int j = 0; j < 8; j++) {
            int i = threadIdx.x + j * THREADS;
            if (i < F4_PER_TILE) s4t[i] = rt[j];
        }
    }
    __syncthreads();

    const float* p = sp + threadIdx.x * 30;
    const float* t = st + threadIdx.x * 30;

    float loss;
    bool obj = (t[4] > 0.0f);   // target conf is exactly 0.0 or 1.0

    if (obj) {
        // ---- class loss: sum_{c=10..29} (p-t)^2 ----
        float cls = 0.0f;
#pragma unroll
        for (int c = 10; c < 30; c++) {
            float d = p[c] - t[c];
            cls = fmaf(d, d, cls);
        }

        // ---- IoU of both pred boxes vs target box 0 ----
        const float invS = 1.0f / (float)SGRID;
        float tcx = t[0] * invS, tcy = t[1] * invS;
        float t1x = tcx - t[2] * 0.5f, t2x = tcx + t[2] * 0.5f;
        float t1y = tcy - t[3] * 0.5f, t2y = tcy + t[3] * 0.5f;
        float area_t = (t2x - t1x) * (t2y - t1y);

        float iou0, iou1;
#pragma unroll
        for (int b = 0; b < 2; b++) {
            float bx = (b == 0) ? p[0] : p[5];
            float by = (b == 0) ? p[1] : p[6];
            float bw = (b == 0) ? p[2] : p[7];
            float bh = (b == 0) ? p[3] : p[8];
            float cx = bx * invS, cy = by * invS;
            float p1x = cx - bw * 0.5f, p2x = cx + bw * 0.5f;
            float p1y = cy - bh * 0.5f, p2y = cy + bh * 0.5f;
            float ltx = fmaxf(p1x, t1x), lty = fmaxf(p1y, t1y);
            float rbx = fminf(p2x, t2x), rby = fminf(p2y, t2y);
            float wx = fmaxf(rbx - ltx, 0.0f);
            float wy = fmaxf(rby - lty, 0.0f);
            float inter = wx * wy;
            float area_p = (p2x - p1x) * (p2y - p1y);
            float iou = inter / (area_p + area_t - inter);
            if (b == 0) iou0 = iou; else iou1 = iou;
        }

        bool pick1 = (iou0 <= iou1);
        float iou_best = pick1 ? iou1 : iou0;

        float psx = pick1 ? p[5] : p[0];
        float psy = pick1 ? p[6] : p[1];
        float psw = pick1 ? p[7] : p[2];
        float psh = pick1 ? p[8] : p[3];
        float psc = pick1 ? p[9] : p[4];
        float tsx = pick1 ? t[5] : t[0];
        float tsy = pick1 ? t[6] : t[1];
        float tsw = pick1 ? t[7] : t[2];
        float tsh = pick1 ? t[8] : t[3];

        float dx = psx - tsx, dy = psy - tsy;
        float dw = sqrtf(psw) - sqrtf(tsw);
        float dh = sqrtf(psh) - sqrtf(tsh);
        float reg = dx*dx + dy*dy + dw*dw + dh*dh;

        float dc = psc - iou_best;

        loss = cls + 5.0f * reg + dc * dc;
    } else {
        // ---- no-object loss on both confidences ----
        float d4 = p[4] - t[4];
        float d9 = p[9] - t[9];
        loss = 0.5f * (d4 * d4 + d9 * d9);
    }

    // ---- reduction: warp shfl -> smem -> one atomic per block ----
#pragma unroll
    for (int o = 16; o > 0; o >>= 1)
        loss += __shfl_xor_sync(0xffffffffu, loss, o);

    __shared__ float warp_sums[THREADS / 32];
    int wid = threadIdx.x >> 5;
    int lid = threadIdx.x & 31;
    if (lid == 0) warp_sums[wid] = loss;
    __syncthreads();

    if (wid == 0) {
        loss = (lid < THREADS / 32) ? warp_sums[lid] : 0.0f;
#pragma unroll
        for (int o = (THREADS / 64); o > 0; o >>= 1)
            loss += __shfl_xor_sync(0xffffffffu, loss, o);
        if (lid == 0)
            atomicAdd(out, loss * (1.0f / (float)BATCH));
    }
}

extern "C" void kernel_launch(void* const* d_in, const int* in_sizes, int n_in,
                              void* d_out, int out_size)
{
    const float* pred = (const float*)d_in[0];
    const float* targ = (const float*)d_in[1];
    float* out = (float*)d_out;
    (void)in_sizes; (void)n_in; (void)out_size;

    init_out_kernel<<<1, 32>>>(out);
    int blocks = NCELLS / CPB;   // 6272
    yolo_loss_kernel<<<blocks, THREADS>>>(pred, targ, out);
}

// round 3
// speedup vs baseline: 1.1923x; 1.1923x over previous
#include <cuda_runtime.h>
#include <cstdint>

#define SGRID 14
#define BATCH 4096
#define NCELLS (BATCH * SGRID * SGRID)   // 802816
#define THREADS 128
#define CPB 128                          // cells per block
#define F4_PER_TENSOR (CPB * 30 / 4)     // 960 float4 per tensor per block
#define F4_TOTAL (2 * F4_PER_TENSOR)     // 1920 -> 15 per thread

__global__ void init_out_kernel(float* out) {
    if (threadIdx.x == 0 && blockIdx.x == 0) out[0] = 0.0f;
}

__device__ __forceinline__ void cp_async16(uint32_t smem_addr, const void* gptr) {
    asm volatile("cp.async.cg.shared.global [%0], [%1], 16;\n"
                 :: "r"(smem_addr), "l"(gptr) : "memory");
}

__global__ void __launch_bounds__(THREADS)
yolo_loss_kernel(const float* __restrict__ pred,
                 const float* __restrict__ targ,
                 float* __restrict__ out)
{
    __shared__ float sbuf[2 * CPB * 30];   // [0 .. 3839] pred, [3840 ..] targ
    float* sp = sbuf;
    float* st = sbuf + CPB * 30;

    const size_t base = (size_t)blockIdx.x * (CPB * 30);
    const float4* gp = reinterpret_cast<const float4*>(pred + base);
    const float4* gt = reinterpret_cast<const float4*>(targ + base);

    uint32_t sbase = (uint32_t)__cvta_generic_to_shared(sbuf);

    // ---- async coalesced stage: 15 x 16B per thread, zero register traffic ----
#pragma unroll
    for (int j = 0; j < 15; j++) {
        int i = threadIdx.x + j * THREADS;          // 0 .. 1919
        const void* src = (i < F4_PER_TENSOR) ? (const void*)(gp + i)
                                              : (const void*)(gt + (i - F4_PER_TENSOR));
        cp_async16(sbase + (uint32_t)i * 16u, src);
    }
    asm volatile("cp.async.commit_group;\n" ::: "memory");
    asm volatile("cp.async.wait_group 0;\n" ::: "memory");
    __syncthreads();

    const float* p = sp + threadIdx.x * 30;
    const float* t = st + threadIdx.x * 30;

    float loss;
    bool obj = (t[4] > 0.0f);   // target conf is exactly 0.0 or 1.0

    if (obj) {
        // ---- class loss: sum_{c=10..29} (p-t)^2 ----
        float cls = 0.0f;
#pragma unroll
        for (int c = 10; c < 30; c++) {
            float d = p[c] - t[c];
            cls = fmaf(d, d, cls);
        }

        // ---- IoU of both pred boxes vs target box 0 ----
        const float invS = 1.0f / (float)SGRID;
        float tcx = t[0] * invS, tcy = t[1] * invS;
        float t1x = tcx - t[2] * 0.5f, t2x = tcx + t[2] * 0.5f;
        float t1y = tcy - t[3] * 0.5f, t2y = tcy + t[3] * 0.5f;
        float area_t = (t2x - t1x) * (t2y - t1y);

        float iou0, iou1;
#pragma unroll
        for (int b = 0; b < 2; b++) {
            float bx = (b == 0) ? p[0] : p[5];
            float by = (b == 0) ? p[1] : p[6];
            float bw = (b == 0) ? p[2] : p[7];
            float bh = (b == 0) ? p[3] : p[8];
            float cx = bx * invS, cy = by * invS;
            float p1x = cx - bw * 0.5f, p2x = cx + bw * 0.5f;
            float p1y = cy - bh * 0.5f, p2y = cy + bh * 0.5f;
            float ltx = fmaxf(p1x, t1x), lty = fmaxf(p1y, t1y);
            float rbx = fminf(p2x, t2x), rby = fminf(p2y, t2y);
            float wx = fmaxf(rbx - ltx, 0.0f);
            float wy = fmaxf(rby - lty, 0.0f);
            float inter = wx * wy;
            float area_p = (p2x - p1x) * (p2y - p1y);
            float iou = inter / (area_p + area_t - inter);
            if (b == 0) iou0 = iou; else iou1 = iou;
        }

        bool pick1 = (iou0 <= iou1);
        float iou_best = pick1 ? iou1 : iou0;

        float psx = pick1 ? p[5] : p[0];
        float psy = pick1 ? p[6] : p[1];
        float psw = pick1 ? p[7] : p[2];
        float psh = pick1 ? p[8] : p[3];
        float psc = pick1 ? p[9] : p[4];
        float tsx = pick1 ? t[5] : t[0];
        float tsy = pick1 ? t[6] : t[1];
        float tsw = pick1 ? t[7] : t[2];
        float tsh = pick1 ? t[8] : t[3];

        float dx = psx - tsx, dy = psy - tsy;
        float dw = sqrtf(psw) - sqrtf(tsw);
        float dh = sqrtf(psh) - sqrtf(tsh);
        float reg = dx*dx + dy*dy + dw*dw + dh*dh;

        float dc = psc - iou_best;

        loss = cls + 5.0f * reg + dc * dc;
    } else {
        // ---- no-object loss on both confidences ----
        float d4 = p[4] - t[4];
        float d9 = p[9] - t[9];
        loss = 0.5f * (d4 * d4 + d9 * d9);
    }

    // ---- reduction: warp shfl -> smem -> one atomic per block ----
#pragma unroll
    for (int o = 16; o > 0; o >>= 1)
        loss += __shfl_xor_sync(0xffffffffu, loss, o);

    __shared__ float warp_sums[THREADS / 32];
    int wid = threadIdx.x >> 5;
    int lid = threadIdx.x & 31;
    if (lid == 0) warp_sums[wid] = loss;
    __syncthreads();

    if (wid == 0) {
        loss = (lid < THREADS / 32) ? warp_sums[lid] : 0.0f;
#pragma unroll
        for (int o = (THREADS / 64); o > 0; o >>= 1)
            loss += __shfl_xor_sync(0xffffffffu, loss, o);
        if (lid == 0)
            atomicAdd(out, loss * (1.0f / (float)BATCH));
    }
}

extern "C" void kernel_launch(void* const* d_in, const int* in_sizes, int n_in,
                              void* d_out, int out_size)
{
    const float* pred = (const float*)d_in[0];
    const float* targ = (const float*)d_in[1];
    float* out = (float*)d_out;
    (void)in_sizes; (void)n_in; (void)out_size;

    init_out_kernel<<<1, 32>>>(out);
    int blocks = NCELLS / CPB;   // 6272
    yolo_loss_kernel<<<blocks, THREADS>>>(pred, targ, out);
}